// round 13
// baseline (speedup 1.0000x reference)
#include <cuda_runtime.h>
#include <cuda_fp16.h>
#include <cstdint>
#include <cstddef>

// ---------------- problem dims ----------------
#define M_DIM 4096            // B*S
#define K_DIM 4096
#define N_DIM 11008

// ---------------- GEMM tiling ----------------
#define BM 128
#define BN 128
#define BK 64                 // halves per K-chunk = 128 bytes (one SW128 row)
#define NCHUNKS (K_DIM / BK)  // 64
#define NSTAGES 3
#define NTHREADS 128          // 4 warps, warp tile 64x64 (2x2 layout)

#define STAGE_A 0
#define STAGE_B (BM * 128)                    // 16384
#define STAGE_BYTES ((BM + BN) * 128)         // 32768
#define SMEM_TOTAL (NSTAGES * STAGE_BYTES)    // 98304 -> 2 CTAs/SM

// ---------------- scratch (fp16 operands) ----------------
static __device__ __half g_xh[(size_t)M_DIM * K_DIM];
static __device__ __half g_wh[(size_t)N_DIM * K_DIM];

// ---------------- helpers ----------------
__device__ __forceinline__ uint32_t smem_u32(const void* p) {
    uint32_t a;
    asm("{ .reg .u64 t; cvta.to.shared.u64 t, %1; cvt.u32.u64 %0, t; }"
        : "=r"(a) : "l"(p));
    return a;
}

#define CP_ASYNC16(dst, src) \
    asm volatile("cp.async.cg.shared.global [%0], [%1], 16;" \
                 :: "r"(dst), "l"(src) : "memory")

#define LDSM_X4(r0, r1, r2, r3, addr)                                   \
    asm volatile("ldmatrix.sync.aligned.m8n8.x4.shared.b16 "            \
                 "{%0, %1, %2, %3}, [%4];"                              \
                 : "=r"(r0), "=r"(r1), "=r"(r2), "=r"(r3) : "r"(addr))

__device__ __forceinline__ void mma16816(float* d, const uint32_t* a,
                                         uint32_t b0, uint32_t b1) {
    asm volatile(
        "mma.sync.aligned.m16n8k16.row.col.f32.f16.f16.f32 "
        "{%0, %1, %2, %3}, {%4, %5, %6, %7}, {%8, %9}, {%0, %1, %2, %3};"
        : "+f"(d[0]), "+f"(d[1]), "+f"(d[2]), "+f"(d[3])
        : "r"(a[0]), "r"(a[1]), "r"(a[2]), "r"(a[3]), "r"(b0), "r"(b1));
}

// ---------------- conversion kernels (16 elems/thread) ----------------
__global__ void __launch_bounds__(256) conv_x_kernel(const float4* __restrict__ x) {
    size_t i = (size_t)blockIdx.x * 256 + threadIdx.x;   // two uint4 out = 16 halves
    float4 v0 = x[4 * i];
    float4 v1 = x[4 * i + 1];
    float4 v2 = x[4 * i + 2];
    float4 v3 = x[4 * i + 3];
    __half2 h0 = __floats2half2_rn(v0.x, v0.y);
    __half2 h1 = __floats2half2_rn(v0.z, v0.w);
    __half2 h2 = __floats2half2_rn(v1.x, v1.y);
    __half2 h3 = __floats2half2_rn(v1.z, v1.w);
    __half2 h4 = __floats2half2_rn(v2.x, v2.y);
    __half2 h5 = __floats2half2_rn(v2.z, v2.w);
    __half2 h6 = __floats2half2_rn(v3.x, v3.y);
    __half2 h7 = __floats2half2_rn(v3.z, v3.w);
    uint4 o0, o1;
    o0.x = *reinterpret_cast<uint32_t*>(&h0);
    o0.y = *reinterpret_cast<uint32_t*>(&h1);
    o0.z = *reinterpret_cast<uint32_t*>(&h2);
    o0.w = *reinterpret_cast<uint32_t*>(&h3);
    o1.x = *reinterpret_cast<uint32_t*>(&h4);
    o1.y = *reinterpret_cast<uint32_t*>(&h5);
    o1.z = *reinterpret_cast<uint32_t*>(&h6);
    o1.w = *reinterpret_cast<uint32_t*>(&h7);
    reinterpret_cast<uint4*>(g_xh)[2 * i]     = o0;
    reinterpret_cast<uint4*>(g_xh)[2 * i + 1] = o1;
}

__global__ void __launch_bounds__(256) conv_w_kernel(const int4* __restrict__ w) {
    size_t i = (size_t)blockIdx.x * 256 + threadIdx.x;   // two uint4 out = 16 halves
    int4 v0 = w[4 * i];
    int4 v1 = w[4 * i + 1];
    int4 v2 = w[4 * i + 2];
    int4 v3 = w[4 * i + 3];
    __half2 h0 = __halves2half2(__int2half_rn(v0.x), __int2half_rn(v0.y));
    __half2 h1 = __halves2half2(__int2half_rn(v0.z), __int2half_rn(v0.w));
    __half2 h2 = __halves2half2(__int2half_rn(v1.x), __int2half_rn(v1.y));
    __half2 h3 = __halves2half2(__int2half_rn(v1.z), __int2half_rn(v1.w));
    __half2 h4 = __halves2half2(__int2half_rn(v2.x), __int2half_rn(v2.y));
    __half2 h5 = __halves2half2(__int2half_rn(v2.z), __int2half_rn(v2.w));
    __half2 h6 = __halves2half2(__int2half_rn(v3.x), __int2half_rn(v3.y));
    __half2 h7 = __halves2half2(__int2half_rn(v3.z), __int2half_rn(v3.w));
    uint4 o0, o1;
    o0.x = *reinterpret_cast<uint32_t*>(&h0);
    o0.y = *reinterpret_cast<uint32_t*>(&h1);
    o0.z = *reinterpret_cast<uint32_t*>(&h2);
    o0.w = *reinterpret_cast<uint32_t*>(&h3);
    o1.x = *reinterpret_cast<uint32_t*>(&h4);
    o1.y = *reinterpret_cast<uint32_t*>(&h5);
    o1.z = *reinterpret_cast<uint32_t*>(&h6);
    o1.w = *reinterpret_cast<uint32_t*>(&h7);
    reinterpret_cast<uint4*>(g_wh)[2 * i]     = o0;
    reinterpret_cast<uint4*>(g_wh)[2 * i + 1] = o1;
}

// ---------------- GEMM kernel (HMMA, 4 warps @ 64x64, 2 CTAs/SM,
//                  software-pipelined fragment loads) ----------------
__global__ void __launch_bounds__(NTHREADS, 2)
qgemm_kernel(const float* __restrict__ scale, float* __restrict__ out) {
    extern __shared__ char smem[];
    const uint32_t sb = smem_u32(smem);
    const int tid  = threadIdx.x;
    const int wid  = tid >> 5;
    const int lane = tid & 31;
    const int warp_m = wid >> 1;   // 0..1  (64 rows each)
    const int warp_n = wid & 1;    // 0..1  (64 cols each)
    const int m0 = blockIdx.x * BM;
    const int n0 = blockIdx.y * BN;

    // ---- cp.async addressing: 128 threads -> 16 rows x 8 x 16B per replica,
    //      8 replicas each for A and B; row step 16 keeps swizzle XOR invariant.
    const char* ag0;
    const char* bg0;
    uint32_t as0, bs0;
    {
        int r = tid >> 3, c = tid & 7;                  // r: 0..15
        uint32_t bo = (uint32_t)(r * 128 + c * 16);
        uint32_t sw = bo ^ ((bo >> 3) & 0x70);
        ag0 = (const char*)(g_xh + (size_t)m0 * K_DIM) + (size_t)r * (K_DIM * 2) + c * 16;
        bg0 = (const char*)(g_wh + (size_t)n0 * K_DIM) + (size_t)r * (K_DIM * 2) + c * 16;
        as0 = STAGE_A + sw;
        bs0 = STAGE_B + sw;
    }
    const size_t GSTRIDE = (size_t)16 * K_DIM * 2;      // 16 rows of global

    // ---- ldmatrix addressing
    const uint32_t klaA = (lane >> 4) * 16;
    uint32_t aoff0, axor;
    {
        int row = warp_m * 64 + (lane & 15);
        aoff0 = STAGE_A + row * 128;
        axor  = (row & 7) << 4;
    }
    const uint32_t klaB = ((lane >> 3) & 1) * 16;
    uint32_t boff0, bxor;
    {
        int row = warp_n * 64 + ((lane >> 4) << 3) + (lane & 7);
        boff0 = STAGE_B + row * 128;
        bxor  = (row & 7) << 4;
    }

    float acc[4][8][4];
#pragma unroll
    for (int mt = 0; mt < 4; mt++)
#pragma unroll
        for (int nt = 0; nt < 8; nt++)
#pragma unroll
            for (int i = 0; i < 4; i++) acc[mt][nt][i] = 0.0f;

    auto load_chunk = [&](int kc, int s) {
        uint32_t sbase = sb + s * STAGE_BYTES;
        size_t gk = (size_t)kc * 128;   // BK halves = 128 bytes
#pragma unroll
        for (int i = 0; i < 8; i++)
            CP_ASYNC16(sbase + as0 + i * 2048, ag0 + gk + i * GSTRIDE);
#pragma unroll
        for (int i = 0; i < 8; i++)
            CP_ASYNC16(sbase + bs0 + i * 2048, bg0 + gk + i * GSTRIDE);
        asm volatile("cp.async.commit_group;" ::: "memory");
    };

    // Prologue: stages 0,1  (3-stage pipeline, prefetch distance 2)
    load_chunk(0, 0);
    load_chunk(1, 1);

    // Double-buffered fragments.
    uint32_t a[2][4][4];
    uint32_t b[2][4][4];

#pragma unroll 1
    for (int km = 0; km < NCHUNKS; km++) {
        if (km < NCHUNKS - 1) asm volatile("cp.async.wait_group 1;" ::: "memory");
        else                  asm volatile("cp.async.wait_group 0;" ::: "memory");
        __syncthreads();

        if (km + 2 < NCHUNKS) load_chunk(km + 2, (km + 2) % NSTAGES);

        const uint32_t sbase = sb + (km % NSTAGES) * STAGE_BYTES;
        const uint32_t abase = sbase + aoff0;
        const uint32_t bbase = sbase + boff0;

        // Preload ks=0 fragments into buffer 0.
        {
            const uint32_t kbA = klaA ^ axor;
            const uint32_t kbB = klaB ^ bxor;
#pragma unroll
            for (int mt = 0; mt < 4; mt++)
                LDSM_X4(a[0][mt][0], a[0][mt][1], a[0][mt][2], a[0][mt][3],
                        abase + mt * 2048 + kbA);
#pragma unroll
            for (int np = 0; np < 4; np++)
                LDSM_X4(b[0][np][0], b[0][np][1], b[0][np][2], b[0][np][3],
                        bbase + np * 2048 + kbB);
        }

#pragma unroll
        for (int ks = 0; ks < 4; ks++) {
            const int cur = ks & 1;
            const int nxt = cur ^ 1;
            if (ks < 3) {
                const uint32_t kbA = ((ks + 1) * 32 + klaA) ^ axor;
                const uint32_t kbB = ((ks + 1) * 32 + klaB) ^ bxor;
#pragma unroll
                for (int mt = 0; mt < 4; mt++)
                    LDSM_X4(a[nxt][mt][0], a[nxt][mt][1], a[nxt][mt][2], a[nxt][mt][3],
                            abase + mt * 2048 + kbA);
#pragma unroll
                for (int np = 0; np < 4; np++)
                    LDSM_X4(b[nxt][np][0], b[nxt][np][1], b[nxt][np][2], b[nxt][np][3],
                            bbase + np * 2048 + kbB);
            }
#pragma unroll
            for (int mt = 0; mt < 4; mt++)
#pragma unroll
                for (int nt = 0; nt < 8; nt++)
                    mma16816(acc[mt][nt], a[cur][mt],
                             b[cur][nt >> 1][(nt & 1) * 2],
                             b[cur][nt >> 1][(nt & 1) * 2 + 1]);
        }
    }

    // ---- epilogue: scale (fp32), streaming stores (keep L2 for A/B)
    {
        const int gr = lane >> 2;
        const int gc = (lane & 3) * 2;
#pragma unroll
        for (int mt = 0; mt < 4; mt++) {
            const size_t mrow = (size_t)(m0 + warp_m * 64 + mt * 16 + gr);
#pragma unroll
            for (int nt = 0; nt < 8; nt++) {
                const int ncol = n0 + warp_n * 64 + nt * 8 + gc;
                const float2 sc = *reinterpret_cast<const float2*>(scale + ncol);
                float2 v0, v1;
                v0.x = acc[mt][nt][0] * sc.x;
                v0.y = acc[mt][nt][1] * sc.y;
                v1.x = acc[mt][nt][2] * sc.x;
                v1.y = acc[mt][nt][3] * sc.y;
                __stwt(reinterpret_cast<float2*>(out + mrow * N_DIM + ncol), v0);
                __stwt(reinterpret_cast<float2*>(out + (mrow + 8) * N_DIM + ncol), v1);
            }
        }
    }
}

// ---------------- launcher ----------------
extern "C" void kernel_launch(void* const* d_in, const int* in_sizes, int n_in,
                              void* d_out, int out_size) {
    (void)in_sizes; (void)n_in; (void)out_size;
    const float* x     = (const float*)d_in[0];
    const int*   w     = (const int*)d_in[1];
    const float* scale = (const float*)d_in[2];
    float*       out   = (float*)d_out;

    cudaFuncSetAttribute(qgemm_kernel,
                         cudaFuncAttributeMaxDynamicSharedMemorySize, SMEM_TOTAL);

    conv_x_kernel<<<((size_t)M_DIM * K_DIM / 16) / 256, 256>>>((const float4*)x);
    conv_w_kernel<<<((size_t)N_DIM * K_DIM / 16) / 256, 256>>>((const int4*)w);

    dim3 grid(M_DIM / BM, N_DIM / BN);   // (32, 86); x = M tiles -> small L2 set per wave
    qgemm_kernel<<<grid, NTHREADS, SMEM_TOTAL>>>(scale, out);
}

// round 14
// speedup vs baseline: 1.0095x; 1.0095x over previous
#include <cuda_runtime.h>
#include <cuda_fp16.h>
#include <cstdint>
#include <cstddef>

// ---------------- problem dims ----------------
#define M_DIM 4096            // B*S
#define K_DIM 4096
#define N_DIM 11008

// ---------------- GEMM tiling ----------------
#define BM 128
#define BN 128
#define BK 64                 // halves per K-chunk = 128 bytes (one SW128 row)
#define NCHUNKS (K_DIM / BK)  // 64
#define NSTAGES 3
#define NTHREADS 128          // 4 warps, warp tile 64x64 (2x2 layout)

#define STAGE_A 0
#define STAGE_B (BM * 128)                    // 16384
#define STAGE_BYTES ((BM + BN) * 128)         // 32768
#define SMEM_TOTAL (NSTAGES * STAGE_BYTES)    // 98304 -> 2 CTAs/SM

// ---------------- wave-tail split-K ----------------
#define NTILES 2752           // 32 * 86
#define NFULL 2664            // 9 full waves * 296 slots
#define NSPLIT (NTILES - NFULL)        // 88 tiles, split 3-ways
#define GEMM_GRID (NFULL + NSPLIT * 3) // 2928
#define TILE_ELEMS (BM * BN)           // 16384

// ---------------- scratch ----------------
static __device__ __half g_xh[(size_t)M_DIM * K_DIM];
static __device__ __half g_wh[(size_t)N_DIM * K_DIM];
static __device__ float  g_part[3][NSPLIT][TILE_ELEMS];   // split-K partials

// ---------------- helpers ----------------
__device__ __forceinline__ uint32_t smem_u32(const void* p) {
    uint32_t a;
    asm("{ .reg .u64 t; cvta.to.shared.u64 t, %1; cvt.u32.u64 %0, t; }"
        : "=r"(a) : "l"(p));
    return a;
}

#define CP_ASYNC16(dst, src) \
    asm volatile("cp.async.cg.shared.global [%0], [%1], 16;" \
                 :: "r"(dst), "l"(src) : "memory")

#define LDSM_X4(r0, r1, r2, r3, addr)                                   \
    asm volatile("ldmatrix.sync.aligned.m8n8.x4.shared.b16 "            \
                 "{%0, %1, %2, %3}, [%4];"                              \
                 : "=r"(r0), "=r"(r1), "=r"(r2), "=r"(r3) : "r"(addr))

__device__ __forceinline__ void mma16816(float* d, const uint32_t* a,
                                         uint32_t b0, uint32_t b1) {
    asm volatile(
        "mma.sync.aligned.m16n8k16.row.col.f32.f16.f16.f32 "
        "{%0, %1, %2, %3}, {%4, %5, %6, %7}, {%8, %9}, {%0, %1, %2, %3};"
        : "+f"(d[0]), "+f"(d[1]), "+f"(d[2]), "+f"(d[3])
        : "r"(a[0]), "r"(a[1]), "r"(a[2]), "r"(a[3]), "r"(b0), "r"(b1));
}

// ---------------- conversion kernels (8 elems/thread — R12 best) ----------------
__global__ void __launch_bounds__(256) conv_x_kernel(const float4* __restrict__ x) {
    size_t i = (size_t)blockIdx.x * 256 + threadIdx.x;   // one uint4 out = 8 halves
    float4 v0 = x[2 * i];
    float4 v1 = x[2 * i + 1];
    __half2 a = __floats2half2_rn(v0.x, v0.y);
    __half2 b = __floats2half2_rn(v0.z, v0.w);
    __half2 c = __floats2half2_rn(v1.x, v1.y);
    __half2 d = __floats2half2_rn(v1.z, v1.w);
    uint4 o;
    o.x = *reinterpret_cast<uint32_t*>(&a);
    o.y = *reinterpret_cast<uint32_t*>(&b);
    o.z = *reinterpret_cast<uint32_t*>(&c);
    o.w = *reinterpret_cast<uint32_t*>(&d);
    reinterpret_cast<uint4*>(g_xh)[i] = o;
}

__global__ void __launch_bounds__(256) conv_w_kernel(const int4* __restrict__ w) {
    size_t i = (size_t)blockIdx.x * 256 + threadIdx.x;   // one uint4 out = 8 halves
    int4 v0 = w[2 * i];
    int4 v1 = w[2 * i + 1];
    __half2 a = __halves2half2(__int2half_rn(v0.x), __int2half_rn(v0.y));
    __half2 b = __halves2half2(__int2half_rn(v0.z), __int2half_rn(v0.w));
    __half2 c = __halves2half2(__int2half_rn(v1.x), __int2half_rn(v1.y));
    __half2 d = __halves2half2(__int2half_rn(v1.z), __int2half_rn(v1.w));
    uint4 o;
    o.x = *reinterpret_cast<uint32_t*>(&a);
    o.y = *reinterpret_cast<uint32_t*>(&b);
    o.z = *reinterpret_cast<uint32_t*>(&c);
    o.w = *reinterpret_cast<uint32_t*>(&d);
    reinterpret_cast<uint4*>(g_wh)[i] = o;
}

// ---------------- GEMM kernel (HMMA, 4 warps @ 64x64, 2 CTAs/SM,
//                  last-wave tiles split 3-way in K) ----------------
__global__ void __launch_bounds__(NTHREADS, 2)
qgemm_kernel(const float* __restrict__ scale, float* __restrict__ out) {
    extern __shared__ char smem[];
    const uint32_t sb = smem_u32(smem);
    const int tid  = threadIdx.x;
    const int wid  = tid >> 5;
    const int lane = tid & 31;
    const int warp_m = wid >> 1;   // 0..1  (64 rows each)
    const int warp_n = wid & 1;    // 0..1  (64 cols each)

    // ---- tile / K-range assignment
    int t, split, k0, k1;
    {
        const int bid = blockIdx.x;
        if (bid < NFULL) {
            t = bid; split = -1; k0 = 0; k1 = NCHUNKS;
        } else {
            const int idx = bid - NFULL;
            t = NFULL + idx / 3;
            split = idx % 3;
            k0 = (split == 0) ? 0  : (split == 1) ? 22 : 43;
            k1 = (split == 0) ? 22 : (split == 1) ? 43 : 64;
        }
    }
    const int m0 = (t & 31) * BM;   // m-fastest order == old dim3(32,86) traversal
    const int n0 = (t >> 5) * BN;

    // ---- cp.async addressing: 128 threads -> 16 rows x 8 x 16B per replica
    const char* ag0;
    const char* bg0;
    uint32_t as0, bs0;
    {
        int r = tid >> 3, c = tid & 7;                  // r: 0..15
        uint32_t bo = (uint32_t)(r * 128 + c * 16);
        uint32_t sw = bo ^ ((bo >> 3) & 0x70);
        ag0 = (const char*)(g_xh + (size_t)m0 * K_DIM) + (size_t)r * (K_DIM * 2) + c * 16;
        bg0 = (const char*)(g_wh + (size_t)n0 * K_DIM) + (size_t)r * (K_DIM * 2) + c * 16;
        as0 = STAGE_A + sw;
        bs0 = STAGE_B + sw;
    }
    const size_t GSTRIDE = (size_t)16 * K_DIM * 2;      // 16 rows of global

    // ---- ldmatrix addressing
    const uint32_t klaA = (lane >> 4) * 16;
    uint32_t aoff0, axor;
    {
        int row = warp_m * 64 + (lane & 15);
        aoff0 = STAGE_A + row * 128;
        axor  = (row & 7) << 4;
    }
    const uint32_t klaB = ((lane >> 3) & 1) * 16;
    uint32_t boff0, bxor;
    {
        int row = warp_n * 64 + ((lane >> 4) << 3) + (lane & 7);
        boff0 = STAGE_B + row * 128;
        bxor  = (row & 7) << 4;
    }

    float acc[4][8][4];
#pragma unroll
    for (int mt = 0; mt < 4; mt++)
#pragma unroll
        for (int nt = 0; nt < 8; nt++)
#pragma unroll
            for (int i = 0; i < 4; i++) acc[mt][nt][i] = 0.0f;

    auto load_chunk = [&](int kc, int s) {
        uint32_t sbase = sb + s * STAGE_BYTES;
        size_t gk = (size_t)kc * 128;   // BK halves = 128 bytes
#pragma unroll
        for (int i = 0; i < 8; i++)
            CP_ASYNC16(sbase + as0 + i * 2048, ag0 + gk + i * GSTRIDE);
#pragma unroll
        for (int i = 0; i < 8; i++)
            CP_ASYNC16(sbase + bs0 + i * 2048, bg0 + gk + i * GSTRIDE);
        asm volatile("cp.async.commit_group;" ::: "memory");
    };

    // Prologue: first two chunks of this CTA's K-range.
    load_chunk(k0,     k0 % NSTAGES);
    load_chunk(k0 + 1, (k0 + 1) % NSTAGES);

    // Double-buffered fragments.
    uint32_t a[2][4][4];
    uint32_t b[2][4][4];

#pragma unroll 1
    for (int km = k0; km < k1; km++) {
        if (km < k1 - 1) asm volatile("cp.async.wait_group 1;" ::: "memory");
        else             asm volatile("cp.async.wait_group 0;" ::: "memory");
        __syncthreads();

        if (km + 2 < k1) load_chunk(km + 2, (km + 2) % NSTAGES);

        const uint32_t sbase = sb + (km % NSTAGES) * STAGE_BYTES;
        const uint32_t abase = sbase + aoff0;
        const uint32_t bbase = sbase + boff0;

        // Preload ks=0 fragments into buffer 0.
        {
            const uint32_t kbA = klaA ^ axor;
            const uint32_t kbB = klaB ^ bxor;
#pragma unroll
            for (int mt = 0; mt < 4; mt++)
                LDSM_X4(a[0][mt][0], a[0][mt][1], a[0][mt][2], a[0][mt][3],
                        abase + mt * 2048 + kbA);
#pragma unroll
            for (int np = 0; np < 4; np++)
                LDSM_X4(b[0][np][0], b[0][np][1], b[0][np][2], b[0][np][3],
                        bbase + np * 2048 + kbB);
        }

#pragma unroll
        for (int ks = 0; ks < 4; ks++) {
            const int cur = ks & 1;
            const int nxt = cur ^ 1;
            if (ks < 3) {
                const uint32_t kbA = ((ks + 1) * 32 + klaA) ^ axor;
                const uint32_t kbB = ((ks + 1) * 32 + klaB) ^ bxor;
#pragma unroll
                for (int mt = 0; mt < 4; mt++)
                    LDSM_X4(a[nxt][mt][0], a[nxt][mt][1], a[nxt][mt][2], a[nxt][mt][3],
                            abase + mt * 2048 + kbA);
#pragma unroll
                for (int np = 0; np < 4; np++)
                    LDSM_X4(b[nxt][np][0], b[nxt][np][1], b[nxt][np][2], b[nxt][np][3],
                            bbase + np * 2048 + kbB);
            }
#pragma unroll
            for (int mt = 0; mt < 4; mt++)
#pragma unroll
                for (int nt = 0; nt < 8; nt++)
                    mma16816(acc[mt][nt], a[cur][mt],
                             b[cur][nt >> 1][(nt & 1) * 2],
                             b[cur][nt >> 1][(nt & 1) * 2 + 1]);
        }
    }

    // ---- epilogue
    const int gr = lane >> 2;
    const int gc = (lane & 3) * 2;
    if (split < 0) {
        // full tile: scale (fp32) + streaming store to out
#pragma unroll
        for (int mt = 0; mt < 4; mt++) {
            const size_t mrow = (size_t)(m0 + warp_m * 64 + mt * 16 + gr);
#pragma unroll
            for (int nt = 0; nt < 8; nt++) {
                const int ncol = n0 + warp_n * 64 + nt * 8 + gc;
                const float2 sc = *reinterpret_cast<const float2*>(scale + ncol);
                float2 v0, v1;
                v0.x = acc[mt][nt][0] * sc.x;
                v0.y = acc[mt][nt][1] * sc.y;
                v1.x = acc[mt][nt][2] * sc.x;
                v1.y = acc[mt][nt][3] * sc.y;
                __stwt(reinterpret_cast<float2*>(out + mrow * N_DIM + ncol), v0);
                __stwt(reinterpret_cast<float2*>(out + (mrow + 8) * N_DIM + ncol), v1);
            }
        }
    } else {
        // split tile: raw partial to scratch (scale applied in reduce kernel)
        float* pbase = &g_part[split][t - NFULL][0];
#pragma unroll
        for (int mt = 0; mt < 4; mt++) {
            const int row = warp_m * 64 + mt * 16 + gr;
#pragma unroll
            for (int nt = 0; nt < 8; nt++) {
                const int col = warp_n * 64 + nt * 8 + gc;
                float2 v0, v1;
                v0.x = acc[mt][nt][0];
                v0.y = acc[mt][nt][1];
                v1.x = acc[mt][nt][2];
                v1.y = acc[mt][nt][3];
                *reinterpret_cast<float2*>(pbase + row * BN + col)       = v0;
                *reinterpret_cast<float2*>(pbase + (row + 8) * BN + col) = v1;
            }
        }
    }
}

// ---------------- split-K reduce: out = (p0+p1+p2) * scale ----------------
__global__ void __launch_bounds__(256)
reduce_kernel(const float* __restrict__ scale, float* __restrict__ out) {
    const int i = blockIdx.x * 256 + threadIdx.x;    // float2 index
    const int e = i * 2;
    const int tile  = e >> 14;                       // /16384
    const int local = e & (TILE_ELEMS - 1);
    const int row = local >> 7;
    const int col = local & 127;
    const int t  = NFULL + tile;
    const int m0 = (t & 31) * BM;
    const int n0 = (t >> 5) * BN;
    const float2 p0 = *reinterpret_cast<const float2*>(&g_part[0][tile][local]);
    const float2 p1 = *reinterpret_cast<const float2*>(&g_part[1][tile][local]);
    const float2 p2 = *reinterpret_cast<const float2*>(&g_part[2][tile][local]);
    const float2 sc = *reinterpret_cast<const float2*>(scale + n0 + col);
    float2 v;
    v.x = (p0.x + p1.x + p2.x) * sc.x;
    v.y = (p0.y + p1.y + p2.y) * sc.y;
    __stwt(reinterpret_cast<float2*>(out + (size_t)(m0 + row) * N_DIM + n0 + col), v);
}

// ---------------- launcher ----------------
extern "C" void kernel_launch(void* const* d_in, const int* in_sizes, int n_in,
                              void* d_out, int out_size) {
    (void)in_sizes; (void)n_in; (void)out_size;
    const float* x     = (const float*)d_in[0];
    const int*   w     = (const int*)d_in[1];
    const float* scale = (const float*)d_in[2];
    float*       out   = (float*)d_out;

    cudaFuncSetAttribute(qgemm_kernel,
                         cudaFuncAttributeMaxDynamicSharedMemorySize, SMEM_TOTAL);

    conv_x_kernel<<<((size_t)M_DIM * K_DIM / 8) / 256, 256>>>((const float4*)x);
    conv_w_kernel<<<((size_t)N_DIM * K_DIM / 8) / 256, 256>>>((const int4*)w);

    qgemm_kernel<<<GEMM_GRID, NTHREADS, SMEM_TOTAL>>>(scale, out);
    reduce_kernel<<<(NSPLIT * TILE_ELEMS / 2) / 256, 256>>>(scale, out);
}